// round 1
// baseline (speedup 1.0000x reference)
#include <cuda_runtime.h>
#include <cuda_bf16.h>
#include <float.h>

// Problem constants
#define BATCH   8
#define NOBJ    8192
#define MPTS    8192
#define NTOK    1024
#define DLAT    1024
#define DFEAT   512
#define DOUT    1024
#define KDIM    (DLAT + DFEAT)   // 1536

// Scratch (allocation-free rule: __device__ globals)
__device__ int g_nearest[NOBJ];          // nearest precomputed point of obj_pts[0][q]
__device__ int g_fidx[2 * BATCH * NTOK]; // composed feature row index: [s][b][t], s=0 obj/global, s=1 geo/local

// ---------------------------------------------------------------------------
// NN kernel 1: for each obj point q (batch 0), argmin over precomputed_points.
// Distance formula matches reference: aa + bb - 2*ab (fma-chained), first-index
// tie-break. 2 queries per warp, 8 warps/block -> 16 queries/block.
// ---------------------------------------------------------------------------
#define NN_CH 2048

__global__ void __launch_bounds__(256) nn1_kernel(const float* __restrict__ obj_surf,
                                                  const float* __restrict__ pts) {
    __shared__ float s[NN_CH * 3];
    const int warp = threadIdx.x >> 5;
    const int lane = threadIdx.x & 31;
    const int q0 = blockIdx.x * 16 + warp * 2;

    float qx[2], qy[2], qz[2], aa[2];
#pragma unroll
    for (int u = 0; u < 2; u++) {
        const float* p = obj_surf + (size_t)(q0 + u) * 6;  // batch 0, cols 0..2
        qx[u] = p[0]; qy[u] = p[1]; qz[u] = p[2];
        aa[u] = fmaf(qx[u], qx[u], fmaf(qy[u], qy[u], qz[u] * qz[u]));
    }
    float best[2] = {FLT_MAX, FLT_MAX};
    int   bi[2]   = {0, 0};

    for (int nc = 0; nc < MPTS; nc += NN_CH) {
        __syncthreads();
        // chunk of precomputed_points is contiguous: vectorized load
        const float4* src = (const float4*)(pts + (size_t)nc * 3);
        float4* dst = (float4*)s;
        for (int i = threadIdx.x; i < NN_CH * 3 / 4; i += 256) dst[i] = src[i];
        __syncthreads();
#pragma unroll 4
        for (int j = 0; j < NN_CH / 32; j++) {
            const int c = j * 32 + lane;
            const float sx = s[c * 3], sy = s[c * 3 + 1], sz = s[c * 3 + 2];
            const float bb = fmaf(sx, sx, fmaf(sy, sy, sz * sz));
            const int gi = nc + c;
#pragma unroll
            for (int u = 0; u < 2; u++) {
                const float ab = fmaf(qx[u], sx, fmaf(qy[u], sy, qz[u] * sz));
                const float d = aa[u] + bb - 2.0f * ab;
                if (d < best[u]) { best[u] = d; bi[u] = gi; }
            }
        }
    }
#pragma unroll
    for (int u = 0; u < 2; u++) {
        float b = best[u]; int i = bi[u];
#pragma unroll
        for (int off = 16; off > 0; off >>= 1) {
            float ob = __shfl_xor_sync(0xffffffffu, b, off);
            int   oi = __shfl_xor_sync(0xffffffffu, i, off);
            if (ob < b || (ob == b && oi < i)) { b = ob; i = oi; }
        }
        if (lane == 0) g_nearest[q0 + u] = i;
    }
}

// ---------------------------------------------------------------------------
// NN kernel 2: for each (s, b, t): argmin over obj_pts[b] (8192 pts, stride 6),
// then compose with g_nearest -> g_fidx. s=0: global_pc_infos, s=1: local.
// Queries come from batch 0 slice of the pc_infos tensors (reference uses [0]).
// ---------------------------------------------------------------------------
__global__ void __launch_bounds__(256) nn2_kernel(const float* __restrict__ obj_surf,
                                                  const float* __restrict__ gpc,
                                                  const float* __restrict__ lpc) {
    __shared__ float s[NN_CH * 3];
    const int ssel = blockIdx.z;
    const int b    = blockIdx.y;
    const float* pc = (ssel == 0) ? gpc : lpc;
    const int warp = threadIdx.x >> 5;
    const int lane = threadIdx.x & 31;
    const int t0 = blockIdx.x * 16 + warp * 2;

    float qx[2], qy[2], qz[2], aa[2];
#pragma unroll
    for (int u = 0; u < 2; u++) {
        const float* p = pc + (size_t)(t0 + u) * 3;  // batch-0 slice
        qx[u] = p[0]; qy[u] = p[1]; qz[u] = p[2];
        aa[u] = fmaf(qx[u], qx[u], fmaf(qy[u], qy[u], qz[u] * qz[u]));
    }
    float best[2] = {FLT_MAX, FLT_MAX};
    int   bi[2]   = {0, 0};

    const float* cand_base = obj_surf + (size_t)b * NOBJ * 6;
    for (int nc = 0; nc < NOBJ; nc += NN_CH) {
        __syncthreads();
        for (int p = threadIdx.x; p < NN_CH; p += 256) {
            const float* cp = cand_base + (size_t)(nc + p) * 6;
            s[p * 3]     = cp[0];
            s[p * 3 + 1] = cp[1];
            s[p * 3 + 2] = cp[2];
        }
        __syncthreads();
#pragma unroll 4
        for (int j = 0; j < NN_CH / 32; j++) {
            const int c = j * 32 + lane;
            const float sx = s[c * 3], sy = s[c * 3 + 1], sz = s[c * 3 + 2];
            const float bb = fmaf(sx, sx, fmaf(sy, sy, sz * sz));
            const int gi = nc + c;
#pragma unroll
            for (int u = 0; u < 2; u++) {
                const float ab = fmaf(qx[u], sx, fmaf(qy[u], sy, qz[u] * sz));
                const float d = aa[u] + bb - 2.0f * ab;
                if (d < best[u]) { best[u] = d; bi[u] = gi; }
            }
        }
    }
#pragma unroll
    for (int u = 0; u < 2; u++) {
        float bv = best[u]; int i = bi[u];
#pragma unroll
        for (int off = 16; off > 0; off >>= 1) {
            float ob = __shfl_xor_sync(0xffffffffu, bv, off);
            int   oi = __shfl_xor_sync(0xffffffffu, i, off);
            if (ob < bv || (ob == bv && oi < i)) { bv = ob; i = oi; }
        }
        if (lane == 0)
            g_fidx[(ssel * BATCH + b) * NTOK + t0 + u] = g_nearest[i];
    }
}

// ---------------------------------------------------------------------------
// Fused GEMM: out[z] (8192 x 1024) = [cond | feats[fidx]] (8192 x 1536) @ W + bias
// z = 0: obj (obj_cond, W_obj, b_obj, g_fidx[0]); z = 1: geo.
// 128x128x16 tile, 256 threads, 8x8 register block. A-tile loader performs the
// concat + gather on the fly (k < 1024 -> cond, else precomputed_feats[fidx]).
// ---------------------------------------------------------------------------
#define BM 128
#define BN 128
#define BK 16
#define AS_STRIDE 140   // pad to reduce transposed-store bank conflicts, keeps 16B alignment

__global__ void __launch_bounds__(256) gemm_kernel(const float* __restrict__ objc,
                                                   const float* __restrict__ geoc,
                                                   const float* __restrict__ feats,
                                                   const float* __restrict__ Wo,
                                                   const float* __restrict__ bo,
                                                   const float* __restrict__ Wg,
                                                   const float* __restrict__ bg,
                                                   float* __restrict__ out) {
    const int z = blockIdx.z;
    const float* cond = z ? geoc : objc;
    const float* W    = z ? Wg : Wo;
    const float* bias = z ? bg : bo;
    float* C = out + (size_t)z * (BATCH * NTOK) * DOUT;
    const int* fidx = g_fidx + z * BATCH * NTOK;

    __shared__ float As[BK][AS_STRIDE];
    __shared__ float Bs[BK][BN];
    __shared__ int   sF[BM];

    const int by = blockIdx.y;   // row tile (64)
    const int bx = blockIdx.x;   // col tile (8)
    const int tid = threadIdx.x;

    if (tid < BM) sF[tid] = fidx[by * BM + tid];
    __syncthreads();

    float acc[8][8];
#pragma unroll
    for (int i = 0; i < 8; i++)
#pragma unroll
        for (int j = 0; j < 8; j++) acc[i][j] = 0.0f;

    const int ty = tid >> 4;     // 0..15
    const int tx = tid & 15;     // 0..15

    for (int ko = 0; ko < KDIM / BK; ko++) {
        // --- load A tile (with concat/gather) ---
#pragma unroll
        for (int i = 0; i < 2; i++) {
            const int idx = tid + i * 256;       // 0..511
            const int row = idx >> 2;            // 0..127
            const int c4  = idx & 3;             // 0..3
            const int k   = ko * BK + c4 * 4;
            float4 v;
            if (k < DLAT) {
                v = *(const float4*)(cond + (size_t)(by * BM + row) * DLAT + k);
            } else {
                v = *(const float4*)(feats + (size_t)sF[row] * DFEAT + (k - DLAT));
            }
            As[c4 * 4 + 0][row] = v.x;
            As[c4 * 4 + 1][row] = v.y;
            As[c4 * 4 + 2][row] = v.z;
            As[c4 * 4 + 3][row] = v.w;
        }
        // --- load B tile ---
#pragma unroll
        for (int i = 0; i < 2; i++) {
            const int idx = tid + i * 256;
            const int r = idx >> 5;              // 0..15
            const int c = idx & 31;              // 0..31
            float4 v = *(const float4*)(W + (size_t)(ko * BK + r) * DOUT + bx * BN + c * 4);
            *(float4*)&Bs[r][c * 4] = v;
        }
        __syncthreads();

#pragma unroll
        for (int k = 0; k < BK; k++) {
            float a[8], bv[8];
            *(float4*)&a[0]  = *(const float4*)&As[k][ty * 8];
            *(float4*)&a[4]  = *(const float4*)&As[k][ty * 8 + 4];
            *(float4*)&bv[0] = *(const float4*)&Bs[k][tx * 8];
            *(float4*)&bv[4] = *(const float4*)&Bs[k][tx * 8 + 4];
#pragma unroll
            for (int i = 0; i < 8; i++)
#pragma unroll
                for (int j = 0; j < 8; j++)
                    acc[i][j] = fmaf(a[i], bv[j], acc[i][j]);
        }
        __syncthreads();
    }

    // --- epilogue: add bias, store ---
    float bvals[8];
#pragma unroll
    for (int j = 0; j < 8; j++) bvals[j] = __ldg(bias + bx * BN + tx * 8 + j);

#pragma unroll
    for (int i = 0; i < 8; i++) {
        const int m = by * BM + ty * 8 + i;
        float* dst = C + (size_t)m * DOUT + bx * BN + tx * 8;
        float4 v0 = make_float4(acc[i][0] + bvals[0], acc[i][1] + bvals[1],
                                acc[i][2] + bvals[2], acc[i][3] + bvals[3]);
        float4 v1 = make_float4(acc[i][4] + bvals[4], acc[i][5] + bvals[5],
                                acc[i][6] + bvals[6], acc[i][7] + bvals[7]);
        *(float4*)dst = v0;
        *(float4*)(dst + 4) = v1;
    }
}

// ---------------------------------------------------------------------------
// Launcher. Input order (metadata): object_surface, precomputed_points,
// precomputed_feats, geo_cond, obj_cond, local_pc_infos, global_pc_infos,
// W_obj, b_obj, W_geo, b_geo. Output: [obj_out | geo_out], fp32.
// ---------------------------------------------------------------------------
extern "C" void kernel_launch(void* const* d_in, const int* in_sizes, int n_in,
                              void* d_out, int out_size) {
    (void)in_sizes; (void)n_in; (void)out_size;
    const float* obj_surf = (const float*)d_in[0];
    const float* pts      = (const float*)d_in[1];
    const float* feats    = (const float*)d_in[2];
    const float* geo_cond = (const float*)d_in[3];
    const float* obj_cond = (const float*)d_in[4];
    const float* lpc      = (const float*)d_in[5];
    const float* gpc      = (const float*)d_in[6];
    const float* W_obj    = (const float*)d_in[7];
    const float* b_obj    = (const float*)d_in[8];
    const float* W_geo    = (const float*)d_in[9];
    const float* b_geo    = (const float*)d_in[10];
    float* out = (float*)d_out;

    // 1) nearest precomputed point per obj point (batch 0)
    nn1_kernel<<<NOBJ / 16, 256>>>(obj_surf, pts);

    // 2) per-(s,b,t) nearest obj point, composed with g_nearest -> g_fidx
    dim3 g2(NTOK / 16, BATCH, 2);
    nn2_kernel<<<g2, 256>>>(obj_surf, gpc, lpc);

    // 3) fused concat+gather GEMMs (+bias)
    dim3 g3(DOUT / BN, (BATCH * NTOK) / BM, 2);
    gemm_kernel<<<g3, 256>>>(obj_cond, geo_cond, feats,
                             W_obj, b_obj, W_geo, b_geo, out);
}

// round 4
// speedup vs baseline: 2.6412x; 2.6412x over previous
#include <cuda_runtime.h>
#include <cuda_bf16.h>
#include <float.h>
#include <stdint.h>

// Problem constants
#define BATCH   8
#define NOBJ    8192
#define MPTS    8192
#define NTOK    1024
#define DLAT    1024
#define DFEAT   512
#define DOUT    1024
#define KDIM    (DLAT + DFEAT)   // 1536

#define SWZ128(o) ((o) ^ (((o) >> 3) & 0x70))

static __device__ __forceinline__ uint32_t smem_u32(const void* p) {
    uint32_t a;
    asm("{ .reg .u64 t; cvta.to.shared.u64 t, %1; cvt.u32.u64 %0, t; }" : "=r"(a) : "l"(p));
    return a;
}

#define CP_ASYNC16(dst, src) \
    asm volatile("cp.async.cg.shared.global [%0], [%1], 16;" :: "r"(dst), "l"(src) : "memory")
#define CP_COMMIT() asm volatile("cp.async.commit_group;" ::: "memory")
#define CP_WAIT0()  asm volatile("cp.async.wait_group 0;" ::: "memory")

#define LDSM4(r, addr) \
    asm volatile("ldmatrix.sync.aligned.m8n8.x4.shared.b16 {%0,%1,%2,%3}, [%4];" \
        : "=r"((r)[0]), "=r"((r)[1]), "=r"((r)[2]), "=r"((r)[3]) : "r"(addr))

#define MMA16816(c, a, b0, b1) \
    asm volatile("mma.sync.aligned.m16n8k16.row.col.f32.bf16.bf16.f32 " \
        "{%0,%1,%2,%3}, {%4,%5,%6,%7}, {%8,%9}, {%0,%1,%2,%3};" \
        : "+f"((c)[0]), "+f"((c)[1]), "+f"((c)[2]), "+f"((c)[3]) \
        : "r"((a)[0]), "r"((a)[1]), "r"((a)[2]), "r"((a)[3]), "r"(b0), "r"(b1))

// ---------------------------------------------------------------------------
// Device scratch
// ---------------------------------------------------------------------------
__device__ int g_nearest[NOBJ];
__device__ int g_fidx[2 * BATCH * NTOK];
// pre-split weights: [z][part(hi/lo)][n][k], K-major bf16
__device__ __nv_bfloat16 g_Bs[(size_t)2 * 2 * DOUT * KDIM];

// ---------------------------------------------------------------------------
// NN kernel 1 (unchanged, passed R1 with rel_err 0)
// ---------------------------------------------------------------------------
#define NN_CH 2048

__global__ void __launch_bounds__(256) nn1_kernel(const float* __restrict__ obj_surf,
                                                  const float* __restrict__ pts) {
    __shared__ float s[NN_CH * 3];
    const int warp = threadIdx.x >> 5;
    const int lane = threadIdx.x & 31;
    const int q0 = blockIdx.x * 16 + warp * 2;

    float qx[2], qy[2], qz[2], aa[2];
#pragma unroll
    for (int u = 0; u < 2; u++) {
        const float* p = obj_surf + (size_t)(q0 + u) * 6;
        qx[u] = p[0]; qy[u] = p[1]; qz[u] = p[2];
        aa[u] = fmaf(qx[u], qx[u], fmaf(qy[u], qy[u], qz[u] * qz[u]));
    }
    float best[2] = {FLT_MAX, FLT_MAX};
    int   bi[2]   = {0, 0};

    for (int nc = 0; nc < MPTS; nc += NN_CH) {
        __syncthreads();
        const float4* src = (const float4*)(pts + (size_t)nc * 3);
        float4* dst = (float4*)s;
        for (int i = threadIdx.x; i < NN_CH * 3 / 4; i += 256) dst[i] = src[i];
        __syncthreads();
#pragma unroll 4
        for (int j = 0; j < NN_CH / 32; j++) {
            const int c = j * 32 + lane;
            const float sx = s[c * 3], sy = s[c * 3 + 1], sz = s[c * 3 + 2];
            const float bb = fmaf(sx, sx, fmaf(sy, sy, sz * sz));
            const int gi = nc + c;
#pragma unroll
            for (int u = 0; u < 2; u++) {
                const float ab = fmaf(qx[u], sx, fmaf(qy[u], sy, qz[u] * sz));
                const float d = aa[u] + bb - 2.0f * ab;
                if (d < best[u]) { best[u] = d; bi[u] = gi; }
            }
        }
    }
#pragma unroll
    for (int u = 0; u < 2; u++) {
        float b = best[u]; int i = bi[u];
#pragma unroll
        for (int off = 16; off > 0; off >>= 1) {
            float ob = __shfl_xor_sync(0xffffffffu, b, off);
            int   oi = __shfl_xor_sync(0xffffffffu, i, off);
            if (ob < b || (ob == b && oi < i)) { b = ob; i = oi; }
        }
        if (lane == 0) g_nearest[q0 + u] = i;
    }
}

// ---------------------------------------------------------------------------
// NN kernel 2 (unchanged)
// ---------------------------------------------------------------------------
__global__ void __launch_bounds__(256) nn2_kernel(const float* __restrict__ obj_surf,
                                                  const float* __restrict__ gpc,
                                                  const float* __restrict__ lpc) {
    __shared__ float s[NN_CH * 3];
    const int ssel = blockIdx.z;
    const int b    = blockIdx.y;
    const float* pc = (ssel == 0) ? gpc : lpc;
    const int warp = threadIdx.x >> 5;
    const int lane = threadIdx.x & 31;
    const int t0 = blockIdx.x * 16 + warp * 2;

    float qx[2], qy[2], qz[2], aa[2];
#pragma unroll
    for (int u = 0; u < 2; u++) {
        const float* p = pc + (size_t)(t0 + u) * 3;
        qx[u] = p[0]; qy[u] = p[1]; qz[u] = p[2];
        aa[u] = fmaf(qx[u], qx[u], fmaf(qy[u], qy[u], qz[u] * qz[u]));
    }
    float best[2] = {FLT_MAX, FLT_MAX};
    int   bi[2]   = {0, 0};

    const float* cand_base = obj_surf + (size_t)b * NOBJ * 6;
    for (int nc = 0; nc < NOBJ; nc += NN_CH) {
        __syncthreads();
        for (int p = threadIdx.x; p < NN_CH; p += 256) {
            const float* cp = cand_base + (size_t)(nc + p) * 6;
            s[p * 3]     = cp[0];
            s[p * 3 + 1] = cp[1];
            s[p * 3 + 2] = cp[2];
        }
        __syncthreads();
#pragma unroll 4
        for (int j = 0; j < NN_CH / 32; j++) {
            const int c = j * 32 + lane;
            const float sx = s[c * 3], sy = s[c * 3 + 1], sz = s[c * 3 + 2];
            const float bb = fmaf(sx, sx, fmaf(sy, sy, sz * sz));
            const int gi = nc + c;
#pragma unroll
            for (int u = 0; u < 2; u++) {
                const float ab = fmaf(qx[u], sx, fmaf(qy[u], sy, qz[u] * sz));
                const float d = aa[u] + bb - 2.0f * ab;
                if (d < best[u]) { best[u] = d; bi[u] = gi; }
            }
        }
    }
#pragma unroll
    for (int u = 0; u < 2; u++) {
        float bv = best[u]; int i = bi[u];
#pragma unroll
        for (int off = 16; off > 0; off >>= 1) {
            float ob = __shfl_xor_sync(0xffffffffu, bv, off);
            int   oi = __shfl_xor_sync(0xffffffffu, i, off);
            if (ob < bv || (ob == bv && oi < i)) { bv = ob; i = oi; }
        }
        if (lane == 0)
            g_fidx[(ssel * BATCH + b) * NTOK + t0 + u] = g_nearest[i];
    }
}

// ---------------------------------------------------------------------------
// Prep kernel: transpose + bf16-split W[k][n] -> g_Bs[z][part][n][k]
// ---------------------------------------------------------------------------
__global__ void __launch_bounds__(256) prep_kernel(const float* __restrict__ Wo,
                                                   const float* __restrict__ Wg) {
    __shared__ float t[32][33];
    const int z = blockIdx.z;
    const float* W = z ? Wg : Wo;
    const int kb = blockIdx.x * 32, nb = blockIdx.y * 32;
    const int tx = threadIdx.x & 31, ty = threadIdx.x >> 5;
#pragma unroll
    for (int r = 0; r < 4; r++) {
        const int k = kb + ty + r * 8, n = nb + tx;
        t[ty + r * 8][tx] = W[(size_t)k * DOUT + n];
    }
    __syncthreads();
    __nv_bfloat16* Bh = g_Bs + ((size_t)z * 2 + 0) * DOUT * KDIM;
    __nv_bfloat16* Bl = g_Bs + ((size_t)z * 2 + 1) * DOUT * KDIM;
#pragma unroll
    for (int r = 0; r < 4; r++) {
        const int n = nb + ty + r * 8, k = kb + tx;
        const float v = t[tx][ty + r * 8];
        const __nv_bfloat16 h = __float2bfloat16_rn(v);
        const __nv_bfloat16 l = __float2bfloat16_rn(v - __bfloat162float(h));
        Bh[(size_t)n * KDIM + k] = h;
        Bl[(size_t)n * KDIM + k] = l;
    }
}

// ---------------------------------------------------------------------------
// Warp-MMA split-bf16 GEMM: out[z] (8192x1024) = [cond | feats[fidx]] @ W + b
// CTA 128x128, 8 warps (warp tile 32x64), K-chunk 64, double-buffered.
// 3 passes: Ah*Bh + Ah*Bl + Al*Bh  (Al*Bl ~2^-18, neglected)
// ---------------------------------------------------------------------------
#define STAGE    65536          // Ah(16K) Al(16K) Bh(16K) Bl(16K)
#define OFF_AL   16384
#define OFF_BH   32768
#define OFF_BL   49152
#define SMEM_TOT (2 * STAGE + 512)
#define NCHUNK   (KDIM / 64)    // 24

static __device__ __forceinline__ void split4(float4 v, uint2& hi, uint2& lo) {
    const __nv_bfloat16 h0 = __float2bfloat16_rn(v.x), h1 = __float2bfloat16_rn(v.y),
                        h2 = __float2bfloat16_rn(v.z), h3 = __float2bfloat16_rn(v.w);
    const __nv_bfloat16 l0 = __float2bfloat16_rn(v.x - __bfloat162float(h0)),
                        l1 = __float2bfloat16_rn(v.y - __bfloat162float(h1)),
                        l2 = __float2bfloat16_rn(v.z - __bfloat162float(h2)),
                        l3 = __float2bfloat16_rn(v.w - __bfloat162float(h3));
    __nv_bfloat162 hA = __halves2bfloat162(h0, h1), hB = __halves2bfloat162(h2, h3);
    __nv_bfloat162 lA = __halves2bfloat162(l0, l1), lB = __halves2bfloat162(l2, l3);
    hi.x = *(uint32_t*)&hA; hi.y = *(uint32_t*)&hB;
    lo.x = *(uint32_t*)&lA; lo.y = *(uint32_t*)&lB;
}

__global__ void __launch_bounds__(256, 1) gemm_kernel(const float* __restrict__ objc,
                                                      const float* __restrict__ geoc,
                                                      const float* __restrict__ feats,
                                                      const float* __restrict__ bo,
                                                      const float* __restrict__ bg,
                                                      float* __restrict__ out) {
    extern __shared__ char smem[];
    const int z = blockIdx.z;
    const float* cond = z ? geoc : objc;
    const float* bias = z ? bg : bo;
    const __nv_bfloat16* Bz = g_Bs + (size_t)z * 2 * DOUT * KDIM;
    float* C = out + (size_t)z * (BATCH * NTOK) * DOUT;
    const int* fidx = g_fidx + z * BATCH * NTOK;

    const int tid = threadIdx.x;
    const int wid = tid >> 5, L = tid & 31;
    const int wm = wid & 3, wn = wid >> 2;      // warp grid 4 (m) x 2 (n)
    const int m0 = blockIdx.y * 128;
    const int n0 = blockIdx.x * 128;

    const uint32_t sBase = smem_u32(smem);
    int* sF = (int*)(smem + 2 * STAGE);
    if (tid < 128) sF[tid] = fidx[m0 + tid];

    // fragment-load relative swizzled offsets (XOR ks*32 at use site)
    uint32_t aRel[2];
#pragma unroll
    for (int mt = 0; mt < 2; mt++) {
        uint32_t off = (uint32_t)((wm * 32 + mt * 16 + (L & 15)) * 128 + (L >> 4) * 16);
        aRel[mt] = SWZ128(off);
    }
    const int q = L >> 3;
    const int noff = ((q >> 1) << 3) + (L & 7);
    const int khB = q & 1;
    uint32_t bRel[4];
#pragma unroll
    for (int nt = 0; nt < 4; nt++) {
        uint32_t off = (uint32_t)((wn * 64 + nt * 16 + noff) * 128 + khB * 16);
        bRel[nt] = SWZ128(off);
    }

    float acc[2][8][4];
#pragma unroll
    for (int i = 0; i < 2; i++)
#pragma unroll
        for (int j = 0; j < 8; j++)
#pragma unroll
            for (int r = 0; r < 4; r++) acc[i][j][r] = 0.0f;

    float4 aReg[8];

    // ---- helpers as lambdas ----
    auto prefA = [&](int it) {
        const int k0 = it * 64;
#pragma unroll
        for (int i = 0; i < 8; i++) {
            const int idx = i * 256 + tid;
            const int row = idx >> 4, c4 = idx & 15;
            const float* base = (k0 < DLAT)
                ? cond + (size_t)(m0 + row) * DLAT + k0
                : feats + (size_t)sF[row] * DFEAT + (k0 - DLAT);
            aReg[i] = *((const float4*)base + c4);
        }
    };
    auto stsA = [&](int stg) {
        char* st = smem + stg * STAGE;
#pragma unroll
        for (int i = 0; i < 8; i++) {
            const int idx = i * 256 + tid;
            const int row = idx >> 4, c4 = idx & 15;
            uint2 hi, lo;
            split4(aReg[i], hi, lo);
            const uint32_t off = SWZ128((uint32_t)(row * 128 + c4 * 8));
            *(uint2*)(st + off)          = hi;
            *(uint2*)(st + OFF_AL + off) = lo;
        }
    };
    auto loadB = [&](int it, int stg) {
        const int k0 = it * 64;
        const uint32_t dstBase = sBase + stg * STAGE + OFF_BH;
#pragma unroll
        for (int part = 0; part < 2; part++) {
            const __nv_bfloat16* src = Bz + (size_t)part * DOUT * KDIM;
#pragma unroll
            for (int i = 0; i < 4; i++) {
                const int idx = i * 256 + tid;
                const int row = idx >> 3, u = idx & 7;
                const __nv_bfloat16* g = src + (size_t)(n0 + row) * KDIM + k0 + u * 8;
                const uint32_t d = dstBase + part * 16384 + SWZ128((uint32_t)(row * 128 + u * 16));
                CP_ASYNC16(d, g);
            }
        }
    };
    auto compute = [&](int stg) {
        const uint32_t stU = sBase + stg * STAGE;
#pragma unroll
        for (int ks = 0; ks < 4; ks++) {
            const uint32_t kx = (uint32_t)(ks * 32);
            uint32_t ah[2][4], al[2][4];
            LDSM4(ah[0], stU + (aRel[0] ^ kx));
            LDSM4(ah[1], stU + (aRel[1] ^ kx));
            LDSM4(al[0], stU + OFF_AL + (aRel[0] ^ kx));
            LDSM4(al[1], stU + OFF_AL + (aRel[1] ^ kx));
            uint32_t bh[4][4], bl[4][4];
#pragma unroll
            for (int g = 0; g < 4; g++) LDSM4(bh[g], stU + OFF_BH + (bRel[g] ^ kx));
#pragma unroll
            for (int g = 0; g < 4; g++) LDSM4(bl[g], stU + OFF_BL + (bRel[g] ^ kx));
#pragma unroll
            for (int mt = 0; mt < 2; mt++) {
#pragma unroll
                for (int n8 = 0; n8 < 8; n8++) {
                    const int g = n8 >> 1, h = (n8 & 1) * 2;
                    MMA16816(acc[mt][n8], ah[mt], bh[g][h], bh[g][h + 1]);
                    MMA16816(acc[mt][n8], ah[mt], bl[g][h], bl[g][h + 1]);
                    MMA16816(acc[mt][n8], al[mt], bh[g][h], bh[g][h + 1]);
                }
            }
        }
    };

    // ---- prologue: chunk 0 into stage 0 ----
    __syncthreads();            // sF visible
    prefA(0);
    loadB(0, 0);
    CP_COMMIT();
    stsA(0);
    CP_WAIT0();
    __syncthreads();

    // ---- main loop ----
    for (int it = 0; it < NCHUNK; it++) {
        const int cur = it & 1, nxt = cur ^ 1;
        if (it + 1 < NCHUNK) {
            prefA(it + 1);
            loadB(it + 1, nxt);
            CP_COMMIT();
        }
        compute(cur);
        if (it + 1 < NCHUNK) stsA(nxt);
        CP_WAIT0();
        __syncthreads();
    }

    // ---- epilogue: +bias, store ----
#pragma unroll
    for (int mt = 0; mt < 2; mt++) {
        const int row = m0 + wm * 32 + mt * 16 + (L >> 2);
#pragma unroll
        for (int n8 = 0; n8 < 8; n8++) {
            const int col = n0 + wn * 64 + n8 * 8 + (L & 3) * 2;
            const float2 bv = *(const float2*)(bias + col);
            float2 o0, o1;
            o0.x = acc[mt][n8][0] + bv.x;  o0.y = acc[mt][n8][1] + bv.y;
            o1.x = acc[mt][n8][2] + bv.x;  o1.y = acc[mt][n8][3] + bv.y;
            *(float2*)(C + (size_t)row * DOUT + col)       = o0;
            *(float2*)(C + (size_t)(row + 8) * DOUT + col) = o1;
        }
    }
}

// ---------------------------------------------------------------------------
// Launcher
// ---------------------------------------------------------------------------
extern "C" void kernel_launch(void* const* d_in, const int* in_sizes, int n_in,
                              void* d_out, int out_size) {
    (void)in_sizes; (void)n_in; (void)out_size;
    const float* obj_surf = (const float*)d_in[0];
    const float* pts      = (const float*)d_in[1];
    const float* feats    = (const float*)d_in[2];
    const float* geo_cond = (const float*)d_in[3];
    const float* obj_cond = (const float*)d_in[4];
    const float* lpc      = (const float*)d_in[5];
    const float* gpc      = (const float*)d_in[6];
    const float* W_obj    = (const float*)d_in[7];
    const float* b_obj    = (const float*)d_in[8];
    const float* W_geo    = (const float*)d_in[9];
    const float* b_geo    = (const float*)d_in[10];
    float* out = (float*)d_out;

    cudaFuncSetAttribute(gemm_kernel, cudaFuncAttributeMaxDynamicSharedMemorySize, SMEM_TOT);

    // 0) pre-split + transpose weights (independent of NN results)
    prep_kernel<<<dim3(KDIM / 32, DOUT / 32, 2), 256>>>(W_obj, W_geo);

    // 1) nearest precomputed point per obj point (batch 0)
    nn1_kernel<<<NOBJ / 16, 256>>>(obj_surf, pts);

    // 2) per-(s,b,t) nearest obj point, composed with g_nearest -> g_fidx
    dim3 g2(NTOK / 16, BATCH, 2);
    nn2_kernel<<<g2, 256>>>(obj_surf, gpc, lpc);

    // 3) warp-MMA split-bf16 GEMMs (+bias), fused concat/gather in A loader
    dim3 g3(DOUT / 128, (BATCH * NTOK) / 128, 2);
    gemm_kernel<<<g3, 256, SMEM_TOT>>>(obj_cond, geo_cond, feats, b_obj, b_geo, out);
}